// round 3
// baseline (speedup 1.0000x reference)
#include <cuda_runtime.h>

#define M_DIM 1024
#define E_DIM 64
#define S_DIM 2048
#define GS_TOK 8192
#define GEMM_BLOCKS 128
#define FILL_BLOCKS 2048
#define TOTAL_BLOCKS (1 + GEMM_BLOCKS + FILL_BLOCKS)

__device__ float g_proxy_partial[GEMM_BLOCKS * E_DIM];
__device__ int   g_expert[GS_TOK];
__device__ float g_gate[GS_TOK];
__device__ unsigned short g_pos16[GS_TOK];
__device__ unsigned int g_gemm_done;
__device__ unsigned int g_fill_done;

__global__ __launch_bounds__(256)
void k_fused(const float* __restrict__ X, const float* __restrict__ W,
             float* __restrict__ out, long long out_size,
             long long half, int C, long long aux_idx, float aux_scale)
{
    __shared__ union {
        struct { float As[2112]; float Bs[2048]; float proxy[E_DIM]; } g;  // L[64][65] overlays As+Bs
        struct { int hist[64 * E_DIM]; unsigned char rank8[S_DIM]; unsigned char ex8[S_DIM];
                 float red[E_DIM]; float aux; } s;
    } sm;

    int b = blockIdx.x;
    int tid = threadIdx.x;

    if (b == 0) {
        // ----------------- coordinator: scan + aux + scatter -----------------
        int lane = tid & 31;
        unsigned lt = (1u << lane) - 1u;

        // wait for all GEMM blocks (release via threadfence+atomic on producer side)
        if (tid == 0)
            while (*(volatile unsigned int*)&g_gemm_done < GEMM_BLOCKS) __nanosleep(64);
        __syncthreads();
        __threadfence();

        float auxAcc = 0.f;
        const int G = GS_TOK / S_DIM;
        for (int g = 0; g < G; g++) {
            for (int i = tid; i < 64 * E_DIM; i += 256) sm.s.hist[i] = 0;
            __syncthreads();

            // per-32-token-chunk histogram + in-chunk rank
            #pragma unroll
            for (int i = 0; i < 8; i++) {
                int s = i * 256 + tid;
                int e = g_expert[g * S_DIM + s];
                unsigned m = __match_any_sync(0xffffffffu, e);
                int r = __popc(m & lt);
                sm.s.rank8[s] = (unsigned char)r;
                sm.s.ex8[s]   = (unsigned char)e;
                if (r == 0) sm.s.hist[(s >> 5) * E_DIM + e] = __popc(m);
            }
            __syncthreads();

            // exclusive prefix over chunks + aux term
            if (tid < E_DIM) {
                int run = 0;
                for (int c = 0; c < 64; c++) {
                    int v = sm.s.hist[c * E_DIM + tid];
                    sm.s.hist[c * E_DIM + tid] = run;
                    run += v;
                }
                float proxy = 0.f;
                for (int bb = 0; bb < GEMM_BLOCKS / 4; bb++)
                    proxy += g_proxy_partial[(g * (GEMM_BLOCKS / 4) + bb) * E_DIM + tid];
                const float invden = 1.0f / (2048.0f * 1.000001f);
                auxAcc += (proxy * invden) * ((float)run * invden);
            }
            __syncthreads();

            // final positions
            #pragma unroll
            for (int i = 0; i < 8; i++) {
                int s = i * 256 + tid;
                int e = sm.s.ex8[s];
                int pos = sm.s.hist[(s >> 5) * E_DIM + e] + (int)sm.s.rank8[s];
                g_pos16[g * S_DIM + s] = (unsigned short)pos;
            }
            __syncthreads();
        }

        // reduce aux across 64 lanes
        if (tid < E_DIM) sm.s.red[tid] = auxAcc;
        __syncthreads();
        if (tid < 32) {
            float v = sm.s.red[tid] + sm.s.red[tid + 32];
            #pragma unroll
            for (int off = 16; off; off >>= 1)
                v += __shfl_xor_sync(0xffffffffu, v, off);
            if (tid == 0) sm.s.aux = v * aux_scale;
        }

        // wait for all fill blocks, then scatter over the zeroed output
        if (tid == 0)
            while (*(volatile unsigned int*)&g_fill_done < FILL_BLOCKS) __nanosleep(128);
        __syncthreads();
        __threadfence();

        #pragma unroll
        for (int i = 0; i < GS_TOK / 256; i++) {
            int t = i * 256 + tid;
            int pos = g_pos16[t];
            if (pos < C) {
                float v = g_gate[t];
                int e = g_expert[t];
                long long idx = ((long long)t * E_DIM + e) * C + pos;
                out[idx]        = v;
                out[half + idx] = 1.0f;
            }
        }
        if (tid == 0) out[aux_idx] = sm.s.aux;
        __syncthreads();
        if (tid == 0) {   // last block to finish -> safe to reset for next graph replay
            g_gemm_done = 0;
            g_fill_done = 0;
            __threadfence();
        }
    } else if (b <= GEMM_BLOCKS) {
        // ----------------- GEMM: 64 tokens x 64 experts, f32x2 FFMA -----------------
        float* As = sm.g.As;
        float* Bs = sm.g.Bs;
        int tx = tid & 15, ty = tid >> 4;
        if (tid < E_DIM) sm.g.proxy[tid] = 0.f;

        unsigned long long acc2[4][2];
        #pragma unroll
        for (int i = 0; i < 4; i++) { acc2[i][0] = 0ull; acc2[i][1] = 0ull; }

        int tbase = (b - 1) * 64;
        const float* Xb = X + (long long)tbase * M_DIM;

        for (int kt = 0; kt < M_DIM; kt += 32) {
            #pragma unroll
            for (int j = 0; j < 2; j++) {
                int t  = (tid >> 3) + j * 32;
                int kq = tid & 7;
                float4 v = *(const float4*)(Xb + (long long)t * M_DIM + kt + kq * 4);
                float* dst = As + t * 33 + kq * 4;
                dst[0] = v.x; dst[1] = v.y; dst[2] = v.z; dst[3] = v.w;
            }
            #pragma unroll
            for (int j = 0; j < 2; j++) {
                int idx = tid + j * 256;
                int r = idx >> 4, c4 = idx & 15;
                ((float4*)Bs)[r * 16 + c4] = ((const float4*)(W + (long long)(kt + r) * E_DIM))[c4];
            }
            __syncthreads();
            #pragma unroll
            for (int kk = 0; kk < 32; kk++) {
                ulonglong2 bq = *((const ulonglong2*)(Bs + kk * 64) + tx);
                #pragma unroll
                for (int i = 0; i < 4; i++) {
                    float a = As[(ty * 4 + i) * 33 + kk];
                    unsigned long long ap;
                    asm("mov.b64 %0, {%1, %1};" : "=l"(ap) : "f"(a));
                    asm("fma.rn.f32x2 %0, %1, %2, %0;" : "+l"(acc2[i][0]) : "l"(ap), "l"(bq.x));
                    asm("fma.rn.f32x2 %0, %1, %2, %0;" : "+l"(acc2[i][1]) : "l"(ap), "l"(bq.y));
                }
            }
            __syncthreads();
        }

        // stage logits into shared [64][65]
        float* L = sm.g.As;
        #pragma unroll
        for (int i = 0; i < 4; i++) {
            float2 v0 = *reinterpret_cast<float2*>(&acc2[i][0]);
            float2 v1 = *reinterpret_cast<float2*>(&acc2[i][1]);
            float* row = L + (ty * 4 + i) * 65 + tx * 4;
            row[0] = v0.x; row[1] = v0.y; row[2] = v1.x; row[3] = v1.y;
        }
        __syncthreads();

        int w = tid >> 5, lane = tid & 31;
        float p0 = 0.f, p1 = 0.f;
        #pragma unroll
        for (int i = 0; i < 8; i++) {
            int row = w * 8 + i;
            float L0 = L[row * 65 + lane];
            float L1 = L[row * 65 + lane + 32];
            float v; int idx;
            if (L0 >= L1) { v = L0; idx = lane; } else { v = L1; idx = lane + 32; }
            #pragma unroll
            for (int off = 16; off; off >>= 1) {
                float ov = __shfl_xor_sync(0xffffffffu, v, off);
                int   oi = __shfl_xor_sync(0xffffffffu, idx, off);
                if (ov > v || (ov == v && oi < idx)) { v = ov; idx = oi; }
            }
            float e0 = expf(L0 - v);
            float e1 = expf(L1 - v);
            float s = e0 + e1;
            #pragma unroll
            for (int off = 16; off; off >>= 1)
                s += __shfl_xor_sync(0xffffffffu, s, off);
            float inv = 1.0f / s;
            p0 += e0 * inv;
            p1 += e1 * inv;
            if (lane == 0) {
                int t = tbase + row;
                g_expert[t] = idx;
                g_gate[t]   = inv;
            }
        }
        atomicAdd(&sm.g.proxy[lane], p0);
        atomicAdd(&sm.g.proxy[lane + 32], p1);
        __syncthreads();
        if (tid < E_DIM) g_proxy_partial[(b - 1) * E_DIM + tid] = sm.g.proxy[tid];

        // release: signal done
        __threadfence();
        __syncthreads();
        if (tid == 0) atomicAdd(&g_gemm_done, 1u);
    } else {
        // ----------------- zero fill (contiguous chunks, streaming stores) ----------
        long long n4  = out_size >> 2;
        long long fb  = b - 1 - GEMM_BLOCKS;
        long long per = n4 / FILL_BLOCKS;
        long long rem = n4 - per * FILL_BLOCKS;
        long long base = fb * per + (fb < rem ? fb : rem);
        if (fb < rem) per++;

        float4 z = make_float4(0.f, 0.f, 0.f, 0.f);
        float4* dst = (float4*)out + base;
        long long i = tid;
        for (; i + 768 < per; i += 1024) {
            __stcs(dst + i,       z);
            __stcs(dst + i + 256, z);
            __stcs(dst + i + 512, z);
            __stcs(dst + i + 768, z);
        }
        for (; i < per; i += 256) __stcs(dst + i, z);

        if (fb == 0) {  // scalar tail (aux slot region) — overwritten later by coordinator
            for (long long t = n4 * 4 + tid; t < out_size; t += 256)
                out[t] = 0.f;
        }

        // release: signal done
        __threadfence();
        __syncthreads();
        if (tid == 0) atomicAdd(&g_fill_done, 1u);
    }
}

extern "C" void kernel_launch(void* const* d_in, const int* in_sizes, int n_in,
                              void* d_out, int out_size)
{
    const float* X = (const float*)d_in[0];
    const float* W = (const float*)d_in[1];
    float* out = (float*)d_out;

    long long osz  = (long long)out_size;
    long long half = (osz - 1) / 2;
    int GS = in_sizes[0] / M_DIM;                    // 8192
    int C  = (int)(half / ((long long)GS * E_DIM));  // 160
    int G  = GS / S_DIM;                             // 4
    float aux_scale = (float)((double)E_DIM * E_DIM * 0.01 / ((double)G * E_DIM));

    k_fused<<<TOTAL_BLOCKS, 256>>>(X, W, out, osz, half, C, osz - 1, aux_scale);
}

// round 4
// speedup vs baseline: 1.0985x; 1.0985x over previous
#include <cuda_runtime.h>

#define M_DIM 1024
#define E_DIM 64
#define S_DIM 2048
#define GS_TOK 8192
#define GEMM_BLOCKS 256      // 32 tokens per block
#define FILL_BLOCKS 2048

__device__ float g_proxy_partial[GEMM_BLOCKS * E_DIM];
__device__ int   g_expert[GS_TOK];
__device__ float g_gate[GS_TOK];
__device__ float g_group_loss[8];
__device__ unsigned int g_loss_cnt;

// ---------------------------------------------------------------------------
// K1: fused zero-fill + gating GEMM (32 tokens/block, 2x4 tile, f32x2 FFMA)
// __launch_bounds__(256,6): cap regs ~42 so fill path gets 6 blocks/SM (75% occ)
// ---------------------------------------------------------------------------
__global__ __launch_bounds__(256, 6)
void k1_gemm_fill(const float* __restrict__ X, const float* __restrict__ W,
                  float* __restrict__ out, long long out_size)
{
    __shared__ float smem[3104];   // As[32][33]=1056 + Bs[32][64]=2048; L[32][65]=2080 overlays
    __shared__ float proxyS[E_DIM];

    int b = blockIdx.x;
    int tid = threadIdx.x;

    if (b < GEMM_BLOCKS) {
        if (b == 0 && tid == 0) g_loss_cnt = 0;

        float* As = smem;          // [32][33]
        float* Bs = smem + 1056;   // [32][64]
        int tx = tid & 15, ty = tid >> 4;
        if (tid < E_DIM) proxyS[tid] = 0.f;

        unsigned long long acc2[2][2];
        acc2[0][0] = acc2[0][1] = acc2[1][0] = acc2[1][1] = 0ull;

        int tbase = b * 32;
        const float* Xb = X + (long long)tbase * M_DIM;

        for (int kt = 0; kt < M_DIM; kt += 32) {
            // A tile: 32 tokens x 32 k = 256 float4, one per thread
            {
                int t  = tid >> 3;          // 0..31
                int kq = tid & 7;           // float4 within 32 k
                float4 v = *(const float4*)(Xb + (long long)t * M_DIM + kt + kq * 4);
                float* dst = As + t * 33 + kq * 4;
                dst[0] = v.x; dst[1] = v.y; dst[2] = v.z; dst[3] = v.w;
            }
            // B tile: 32 k x 64 experts = 512 float4, two per thread
            #pragma unroll
            for (int j = 0; j < 2; j++) {
                int idx = tid + j * 256;
                int r = idx >> 4, c4 = idx & 15;
                ((float4*)Bs)[r * 16 + c4] = ((const float4*)(W + (long long)(kt + r) * E_DIM))[c4];
            }
            __syncthreads();
            #pragma unroll
            for (int kk = 0; kk < 32; kk++) {
                ulonglong2 bq = *((const ulonglong2*)(Bs + kk * 64) + tx);
                #pragma unroll
                for (int i = 0; i < 2; i++) {
                    float a = As[(ty * 2 + i) * 33 + kk];
                    unsigned long long ap;
                    asm("mov.b64 %0, {%1, %1};" : "=l"(ap) : "f"(a));
                    asm("fma.rn.f32x2 %0, %1, %2, %0;" : "+l"(acc2[i][0]) : "l"(ap), "l"(bq.x));
                    asm("fma.rn.f32x2 %0, %1, %2, %0;" : "+l"(acc2[i][1]) : "l"(ap), "l"(bq.y));
                }
            }
            __syncthreads();
        }

        // Stage logits to shared [32][65]
        float* L = smem;
        #pragma unroll
        for (int i = 0; i < 2; i++) {
            float2 v0 = *reinterpret_cast<float2*>(&acc2[i][0]);
            float2 v1 = *reinterpret_cast<float2*>(&acc2[i][1]);
            float* row = L + (ty * 2 + i) * 65 + tx * 4;
            row[0] = v0.x; row[1] = v0.y; row[2] = v1.x; row[3] = v1.y;
        }
        __syncthreads();

        // Softmax + argmax: warp w handles 4 tokens; lane covers experts {lane, lane+32}
        int w = tid >> 5, lane = tid & 31;
        float p0 = 0.f, p1 = 0.f;
        #pragma unroll
        for (int i = 0; i < 4; i++) {
            int row = w * 4 + i;
            float L0 = L[row * 65 + lane];
            float L1 = L[row * 65 + lane + 32];
            float v; int idx;
            if (L0 >= L1) { v = L0; idx = lane; } else { v = L1; idx = lane + 32; }
            #pragma unroll
            for (int off = 16; off; off >>= 1) {
                float ov = __shfl_xor_sync(0xffffffffu, v, off);
                int   oi = __shfl_xor_sync(0xffffffffu, idx, off);
                if (ov > v || (ov == v && oi < idx)) { v = ov; idx = oi; }
            }
            float e0 = expf(L0 - v);
            float e1 = expf(L1 - v);
            float s = e0 + e1;
            #pragma unroll
            for (int off = 16; off; off >>= 1)
                s += __shfl_xor_sync(0xffffffffu, s, off);
            float inv = 1.0f / s;
            p0 += e0 * inv;
            p1 += e1 * inv;
            if (lane == 0) {
                int t = tbase + row;
                g_expert[t] = idx;
                g_gate[t]   = inv;
            }
        }
        atomicAdd(&proxyS[lane], p0);
        atomicAdd(&proxyS[lane + 32], p1);
        __syncthreads();
        if (tid < E_DIM) g_proxy_partial[b * E_DIM + tid] = proxyS[tid];
    } else {
        // Contiguous-chunk zero fill with streaming stores
        long long n4  = out_size >> 2;
        long long fb  = b - GEMM_BLOCKS;
        long long per = n4 / FILL_BLOCKS;
        long long rem = n4 - per * FILL_BLOCKS;
        long long base = fb * per + (fb < rem ? fb : rem);
        if (fb < rem) per++;

        float4 z = make_float4(0.f, 0.f, 0.f, 0.f);
        float4* dst = (float4*)out + base;
        long long i = tid;
        for (; i + 768 < per; i += 1024) {
            __stcs(dst + i,       z);
            __stcs(dst + i + 256, z);
            __stcs(dst + i + 512, z);
            __stcs(dst + i + 768, z);
        }
        for (; i < per; i += 256) __stcs(dst + i, z);

        if (fb == 0) {  // scalar tail incl. aux slot
            for (long long t = n4 * 4 + tid; t < out_size; t += 256)
                out[t] = 0.f;
        }
    }
}

// ---------------------------------------------------------------------------
// K2: position-in-expert scan + capacity drop + direct scatter + aux loss
// ---------------------------------------------------------------------------
__global__ __launch_bounds__(1024)
void k2_scan_scatter(float* __restrict__ out, long long half, int C,
                     long long aux_idx, float aux_scale, int G)
{
    __shared__ int hist[64 * E_DIM];
    __shared__ unsigned char rank8[S_DIM];
    __shared__ unsigned char ex8[S_DIM];
    __shared__ float redS[E_DIM];

    int g = blockIdx.x;
    int tid = threadIdx.x;
    for (int i = tid; i < 64 * E_DIM; i += 1024) hist[i] = 0;
    __syncthreads();

    int lane = tid & 31;
    unsigned lt = (1u << lane) - 1u;

    #pragma unroll
    for (int h = 0; h < 2; h++) {
        int s = h * 1024 + tid;
        int e = g_expert[g * S_DIM + s];
        unsigned m = __match_any_sync(0xffffffffu, e);
        int r = __popc(m & lt);
        rank8[s] = (unsigned char)r;
        ex8[s]   = (unsigned char)e;
        if (r == 0) hist[(s >> 5) * E_DIM + e] = __popc(m);
    }
    __syncthreads();

    if (tid < E_DIM) {
        int run = 0;
        for (int c = 0; c < 64; c++) {
            int v = hist[c * E_DIM + tid];
            hist[c * E_DIM + tid] = run;
            run += v;
        }
        float proxy = 0.f;
        for (int bb = 0; bb < GEMM_BLOCKS / 4; bb++)
            proxy += g_proxy_partial[(g * (GEMM_BLOCKS / 4) + bb) * E_DIM + tid];
        const float invden = 1.0f / (2048.0f * 1.000001f);
        redS[tid] = (proxy * invden) * ((float)run * invden);
    }
    __syncthreads();
    if (tid < 32) {
        float v = redS[tid] + redS[tid + 32];
        #pragma unroll
        for (int off = 16; off; off >>= 1)
            v += __shfl_xor_sync(0xffffffffu, v, off);
        if (tid == 0) {
            g_group_loss[g] = v;
            __threadfence();
            atomicAdd(&g_loss_cnt, 1u);
        }
    }

    if (g == 0 && tid == 0) {
        while (atomicAdd(&g_loss_cnt, 0u) < (unsigned)G) { }
        float a = 0.f;
        for (int gg = 0; gg < G; gg++) a += g_group_loss[gg];
        out[aux_idx] = a * aux_scale;
    }
    __syncthreads();

    #pragma unroll
    for (int h = 0; h < 2; h++) {
        int s = h * 1024 + tid;
        int e = ex8[s];
        int pos = hist[(s >> 5) * E_DIM + e] + (int)rank8[s];
        int t = g * S_DIM + s;
        if (pos < C) {
            float v = g_gate[t];
            long long idx = ((long long)t * E_DIM + e) * C + pos;
            out[idx]        = v;
            out[half + idx] = 1.0f;
        }
    }
}

extern "C" void kernel_launch(void* const* d_in, const int* in_sizes, int n_in,
                              void* d_out, int out_size)
{
    const float* X = (const float*)d_in[0];
    const float* W = (const float*)d_in[1];
    float* out = (float*)d_out;

    long long osz  = (long long)out_size;
    long long half = (osz - 1) / 2;
    int GS = in_sizes[0] / M_DIM;                    // 8192
    int C  = (int)(half / ((long long)GS * E_DIM));  // 160
    int G  = GS / S_DIM;                             // 4
    float aux_scale = (float)((double)E_DIM * E_DIM * 0.01 / ((double)G * E_DIM));

    k1_gemm_fill<<<GEMM_BLOCKS + FILL_BLOCKS, 256>>>(X, W, out, osz);
    k2_scan_scatter<<<G, 1024>>>(out, half, C, osz - 1, aux_scale, G);
}